// round 15
// baseline (speedup 1.0000x reference)
#include <cuda_runtime.h>
#include <cuda_fp16.h>
#include <cstdint>

// Problem dims
#define BB 8
#define TT 1024
#define CC 2048
#define MM (BB * TT)          // 8192
#define NELEM (BB * TT * CC)  // 16,777,216

// WKV chunking
#define NCHK 32
#define LCHK (TT / NCHK)      // 32
#define WCHAN 32              // channels per wkv block
#define WTHR (NCHK * WCHAN / 2)  // 512 threads

// GEMM tiling (HMMA mma.sync, fp16, BK=64, 3-stage pipeline)
#define BM 256
#define BN 128
#define BKK 64
#define NITER (CC / BKK)      // 32
#define SROWB 144             // 64 fp16 = 128B + 16B pad
#define TILEA (BM * SROWB)    // 36864
#define TILEB2 (BN * SROWB)   // 18432
#define STAGEB (TILEA + TILEB2)  // 55296
#define NSTAGE 3
#define GSMEM (NSTAGE * STAGEB)  // 165888
#define GTHR 512

#define MIXBLK ((NELEM / 8) / 256)       // 8192 blocks for mixing (8 elem/thr)
#define CVTBLK ((4 * CC * CC / 8) / 256) // 8192 blocks for weight cvt

// ---------------------------------------------------------------------------
// Scratch (static device globals; no allocation anywhere)
// ---------------------------------------------------------------------------
__device__ __half g_xk16[NELEM], g_xv16[NELEM], g_xr16[NELEM];
__device__ __half g_w16[4ULL * CC * CC];
__device__ __half g_k16[NELEM], g_v16[NELEM], g_r16[NELEM];
__device__ __half g_s16[NELEM];

// ---------------------------------------------------------------------------
// Helpers
// ---------------------------------------------------------------------------
__device__ __forceinline__ uint32_t smem_u32(const void* p) {
    uint32_t a;
    asm("{ .reg .u64 t; cvta.to.shared.u64 t, %1; cvt.u32.u64 %0, t; }"
        : "=r"(a) : "l"(p));
    return a;
}
__device__ __forceinline__ void cp_async16(uint32_t saddr, const void* gaddr) {
    asm volatile("cp.async.cg.shared.global [%0], [%1], 16;"
                 :: "r"(saddr), "l"(gaddr));
}
__device__ __forceinline__ void cp_commit() { asm volatile("cp.async.commit_group;"); }
__device__ __forceinline__ void cp_wait1() { asm volatile("cp.async.wait_group 1;"); }
__device__ __forceinline__ void cp_wait0() { asm volatile("cp.async.wait_group 0;"); }

__device__ __forceinline__ void ldsm_x4(uint32_t addr, uint32_t& r0, uint32_t& r1,
                                        uint32_t& r2, uint32_t& r3) {
    asm volatile("ldmatrix.sync.aligned.m8n8.x4.shared.b16 {%0,%1,%2,%3}, [%4];"
                 : "=r"(r0), "=r"(r1), "=r"(r2), "=r"(r3) : "r"(addr));
}
__device__ __forceinline__ void mma_f16(float* c, const uint32_t* a, const uint32_t* b) {
    asm volatile(
        "mma.sync.aligned.m16n8k16.row.col.f32.f16.f16.f32 "
        "{%0,%1,%2,%3}, {%4,%5,%6,%7}, {%8,%9}, {%0,%1,%2,%3};"
        : "+f"(c[0]), "+f"(c[1]), "+f"(c[2]), "+f"(c[3])
        : "r"(a[0]), "r"(a[1]), "r"(a[2]), "r"(a[3]), "r"(b[0]), "r"(b[1]));
}

// pack 8 floats -> one 16B store of 8 fp16
__device__ __forceinline__ void store_h8(__half* __restrict__ dst, size_t base,
                                         float4 a, float4 b) {
    __half2 h0 = __floats2half2_rn(a.x, a.y);
    __half2 h1 = __floats2half2_rn(a.z, a.w);
    __half2 h2 = __floats2half2_rn(b.x, b.y);
    __half2 h3 = __floats2half2_rn(b.z, b.w);
    uint4 u;
    u.x = *reinterpret_cast<uint32_t*>(&h0);
    u.y = *reinterpret_cast<uint32_t*>(&h1);
    u.z = *reinterpret_cast<uint32_t*>(&h2);
    u.w = *reinterpret_cast<uint32_t*>(&h3);
    *reinterpret_cast<uint4*>(dst + base) = u;
}

__device__ __forceinline__ float4 mix4(float4 xc, float4 xs, float4 m) {
    float4 o;
    o.x = xc.x * m.x + xs.x * (1.f - m.x);
    o.y = xc.y * m.y + xs.y * (1.f - m.y);
    o.z = xc.z * m.z + xs.z * (1.f - m.z);
    o.w = xc.w * m.w + xs.w * (1.f - m.w);
    return o;
}

// ---------------------------------------------------------------------------
// Kernel: fused prep — blocks [0, MIXBLK) do time-shift mixing (+cvt),
// blocks [MIXBLK, MIXBLK+CVTBLK) convert the 4 weight matrices.
// 8 elements per thread; all stores are 16B.
// ---------------------------------------------------------------------------
__global__ void prep_kernel(const float4* __restrict__ x4,
                            const float4* __restrict__ tmk4,
                            const float4* __restrict__ tmv4,
                            const float4* __restrict__ tmr4,
                            const float4* __restrict__ w0,
                            const float4* __restrict__ w1,
                            const float4* __restrict__ w2,
                            const float4* __restrict__ w3,
                            __half* __restrict__ wdst) {
    const int blk = blockIdx.x;
    if (blk < MIXBLK) {
        const int C4 = CC / 4;      // 512 float4 per row
        const int C8 = CC / 8;      // 256 groups of 8 per row
        int i = blk * 256 + threadIdx.x;        // [0, NELEM/8)
        int c8 = i % C8;
        int t = (i / C8) % TT;
        int b4 = i * 2;                          // float4 index of first half

        float4 xc0 = x4[b4], xc1 = x4[b4 + 1];
        float4 xs0 = make_float4(0.f, 0.f, 0.f, 0.f);
        float4 xs1 = xs0;
        if (t > 0) { xs0 = x4[b4 - C4]; xs1 = x4[b4 + 1 - C4]; }

        float4 mk0 = tmk4[c8 * 2], mk1 = tmk4[c8 * 2 + 1];
        float4 mv0 = tmv4[c8 * 2], mv1 = tmv4[c8 * 2 + 1];
        float4 mr0 = tmr4[c8 * 2], mr1 = tmr4[c8 * 2 + 1];

        size_t base = (size_t)i * 8;
        store_h8(g_xk16, base, mix4(xc0, xs0, mk0), mix4(xc1, xs1, mk1));
        store_h8(g_xv16, base, mix4(xc0, xs0, mv0), mix4(xc1, xs1, mv1));
        store_h8(g_xr16, base, mix4(xc0, xs0, mr0), mix4(xc1, xs1, mr1));
    } else {
        const int n8 = CC * CC / 8;
        int i = (blk - MIXBLK) * 256 + threadIdx.x;   // [0, 4*n8)
        int m = i / n8;
        int o = i - m * n8;
        const float4* src = (m == 0) ? w0 : (m == 1) ? w1 : (m == 2) ? w2 : w3;
        store_h8(wdst, (size_t)i * 8, src[o * 2], src[o * 2 + 1]);
    }
}

// ---------------------------------------------------------------------------
// Kernel: fp16 HMMA GEMM, CTA 256x128, 512 threads (warp grid 4x4, 64x32 each),
// BK=64, 3-stage cp.async pipeline, one sync/iter. Per-thread inner loop is
// identical to the proven R12 structure; only the CTA shape changed (25% less
// cp.async/STS traffic per output area).
// proj=1: gridDim.z selects (A,B,Ch); all outputs fp16.
// proj=0: fp32 output (the final Wo GEMM into d_out).
// ---------------------------------------------------------------------------
__global__ __launch_bounds__(GTHR, 1)
void gemm_f16(const __half* __restrict__ A0, const __half* __restrict__ A1,
              const __half* __restrict__ A2, const __half* __restrict__ Bbase,
              float* __restrict__ Cf, __half* __restrict__ Ch0,
              __half* __restrict__ Ch1, __half* __restrict__ Ch2, int proj) {
    extern __shared__ __align__(128) char smem[];
    const uint32_t sb = smem_u32(smem);
    const int z = blockIdx.z;
    const __half* A = (z == 0) ? A0 : (z == 1) ? A1 : A2;
    const __half* B = Bbase + (size_t)z * CC * CC;

    const int tid = threadIdx.x;
    const int wid = tid >> 5;
    const int lane = tid & 31;
    const int wm = wid >> 2;          // 0..3
    const int wn = wid & 3;           // 0..3
    const int rowBase = blockIdx.y * BM;
    const int colBase = blockIdx.x * BN;
    const int warpRow = wm * 64;
    const int warpCol = wn * 32;

    const uint32_t OF_A = 0, OF_B = TILEA;

    auto issue_stage = [&](int buf, int k0) {
        uint32_t sbase = sb + buf * STAGEB;
        // A: 256 rows x 8 chunks = 2048 transfers / 512 thr = 4 per thread
#pragma unroll
        for (int it = 0; it < 4; it++) {
            int idx = tid + it * GTHR;
            int r = idx >> 3, c = idx & 7;
            uint32_t so = (uint32_t)(r * SROWB + c * 16);
            size_t gA = (size_t)(rowBase + r) * CC + k0 + c * 8;
            cp_async16(sbase + OF_A + so, A + gA);
        }
        // B: 128 rows x 8 chunks = 1024 transfers / 512 thr = 2 per thread
#pragma unroll
        for (int it = 0; it < 2; it++) {
            int idx = tid + it * GTHR;
            int r = idx >> 3, c = idx & 7;
            uint32_t so = (uint32_t)(r * SROWB + c * 16);
            size_t gB = (size_t)(colBase + r) * CC + k0 + c * 8;
            cp_async16(sbase + OF_B + so, B + gB);
        }
        cp_commit();
    };

    float acc[4][4][4];
#pragma unroll
    for (int i = 0; i < 4; i++)
#pragma unroll
        for (int j = 0; j < 4; j++)
#pragma unroll
            for (int q = 0; q < 4; q++) acc[i][j][q] = 0.f;

    const uint32_t aLaneOff =
        (uint32_t)((warpRow + (lane & 15)) * SROWB + (lane >> 4) * 16);
    const int bg = lane >> 3, bw = lane & 7;
    const uint32_t bLaneOff =
        (uint32_t)((warpCol + (bg >> 1) * 8 + bw) * SROWB + (bg & 1) * 16);

    issue_stage(0, 0);
    issue_stage(1, BKK);

    int buf = 0, nbuf = 2;
#pragma unroll 1
    for (int j = 0; j < NITER; j++) {
        if (j + 2 < NITER) cp_wait1(); else cp_wait0();
        __syncthreads();
        if (j + 2 < NITER) issue_stage(nbuf, (j + 2) * BKK);

        const uint32_t sbase = sb + buf * STAGEB;
#pragma unroll
        for (int kk = 0; kk < 4; kk++) {
            const uint32_t kOff = kk * 32;
            uint32_t ah[4][4], bx[4][2];
#pragma unroll
            for (int i = 0; i < 4; i++) {
                uint32_t ad = sbase + OF_A + aLaneOff + i * 16 * SROWB + kOff;
                ldsm_x4(ad, ah[i][0], ah[i][1], ah[i][2], ah[i][3]);
            }
#pragma unroll
            for (int jp = 0; jp < 2; jp++) {
                uint32_t bd = sbase + OF_B + bLaneOff + jp * 16 * SROWB + kOff;
                ldsm_x4(bd, bx[jp * 2][0], bx[jp * 2][1],
                        bx[jp * 2 + 1][0], bx[jp * 2 + 1][1]);
            }
#pragma unroll
            for (int i = 0; i < 4; i++)
#pragma unroll
                for (int jj = 0; jj < 4; jj++) mma_f16(acc[i][jj], ah[i], bx[jj]);
        }
        buf = (buf == NSTAGE - 1) ? 0 : buf + 1;
        nbuf = (nbuf == NSTAGE - 1) ? 0 : nbuf + 1;
    }

    const int er = lane >> 2, ec = (lane & 3) * 2;
    if (proj) {
        __half* Ch = (z == 0) ? Ch0 : (z == 1) ? Ch1 : Ch2;
#pragma unroll
        for (int i = 0; i < 4; i++) {
#pragma unroll
            for (int jj = 0; jj < 4; jj++) {
                size_t row0 = (size_t)(rowBase + warpRow + i * 16 + er);
                size_t col = (size_t)(colBase + warpCol + jj * 8 + ec);
                __half2 v0 = __floats2half2_rn(acc[i][jj][0], acc[i][jj][1]);
                __half2 v1 = __floats2half2_rn(acc[i][jj][2], acc[i][jj][3]);
                *reinterpret_cast<__half2*>(Ch + row0 * CC + col) = v0;
                *reinterpret_cast<__half2*>(Ch + (row0 + 8) * CC + col) = v1;
            }
        }
    } else {
#pragma unroll
        for (int i = 0; i < 4; i++) {
#pragma unroll
            for (int jj = 0; jj < 4; jj++) {
                size_t row0 = (size_t)(rowBase + warpRow + i * 16 + er);
                size_t col = (size_t)(colBase + warpCol + jj * 8 + ec);
                float2 v0 = make_float2(acc[i][jj][0], acc[i][jj][1]);
                float2 v1 = make_float2(acc[i][jj][2], acc[i][jj][3]);
                *reinterpret_cast<float2*>(Cf + row0 * CC + col) = v0;
                *reinterpret_cast<float2*>(Cf + (row0 + 8) * CC + col) = v1;
            }
        }
    }
}

// ---------------------------------------------------------------------------
// Kernel: fused WKV — all 3 phases in one block per (batch, 32 channels).
// ---------------------------------------------------------------------------
__global__ __launch_bounds__(WTHR)
void wkv_fused(const __half* __restrict__ k,
               const __half* __restrict__ v,
               const __half* __restrict__ r,
               const float* __restrict__ time_decay,
               const float* __restrict__ time_first,
               __half* __restrict__ s) {
    __shared__ float s_v[NCHK][WCHAN];
    __shared__ float s_d[NCHK][WCHAN];
    __shared__ float s_m[NCHK][WCHAN];

    const int b = blockIdx.x / (CC / WCHAN);
    const int cbase = (blockIdx.x % (CC / WCHAN)) * WCHAN;
    const int tid = threadIdx.x;
    const int chunk = tid >> 4;       // 0..31
    const int cp = tid & 15;          // 0..15
    const int c = cbase + cp * 2;

    const float w0 = -__expf(time_decay[c]);
    const float w1 = -__expf(time_decay[c + 1]);
    const float u0 = time_first[c];
    const float u1 = time_first[c + 1];

    const size_t base = ((size_t)b * TT + chunk * LCHK) * CC + c;

    // Phase 1: local sums (zero initial state)
    {
        float sv0 = 0.f, sd0 = 0.f, m0 = -1e38f;
        float sv1 = 0.f, sd1 = 0.f, m1 = -1e38f;
#pragma unroll 4
        for (int t = 0; t < LCHK; t++) {
            size_t g = base + (size_t)t * CC;
            __half2 kh = *reinterpret_cast<const __half2*>(k + g);
            __half2 vh = *reinterpret_cast<const __half2*>(v + g);
            float k0 = __half2float(kh.x), k1 = __half2float(kh.y);
            float v0 = __half2float(vh.x), v1 = __half2float(vh.y);

            float mw0 = m0 + w0, mw1 = m1 + w1;
            float mn0 = fmaxf(mw0, k0), mn1 = fmaxf(mw1, k1);
            float e10 = __expf(mw0 - mn0), e11 = __expf(mw1 - mn1);
            float e20 = __expf(k0 - mn0), e21 = __expf(k1 - mn1);
            sv0 = e10 * sv0 + e20 * v0;  sv1 = e11 * sv1 + e21 * v1;
            sd0 = e10 * sd0 + e20;       sd1 = e11 * sd1 + e21;
            m0 = mn0;                    m1 = mn1;
        }
        s_v[chunk][cp * 2] = sv0;  s_v[chunk][cp * 2 + 1] = sv1;
        s_d[chunk][cp * 2] = sd0;  s_d[chunk][cp * 2 + 1] = sd1;
        s_m[chunk][cp * 2] = m0;   s_m[chunk][cp * 2 + 1] = m1;
    }
    __syncthreads();

    // Phase 2: in-place prefix over chunks; 32 threads, one channel each.
    if (tid < WCHAN) {
        const float w = -__expf(time_decay[cbase + tid]);
        const float Lw = (float)LCHK * w;
        float num = 0.f, den = 0.f, mx = -1e38f;
#pragma unroll
        for (int ch = 0; ch < NCHK; ch++) {
            float svv = s_v[ch][tid];
            float sdd = s_d[ch][tid];
            float smm = s_m[ch][tid];
            s_v[ch][tid] = num;
            s_d[ch][tid] = den;
            s_m[ch][tid] = mx;
            float mo = mx + Lw;
            float mn = fmaxf(mo, smm);
            float e1 = __expf(mo - mn);
            float e2 = __expf(smm - mn);
            num = e1 * num + e2 * svv;
            den = e1 * den + e2 * sdd;
            mx = mn;
        }
    }
    __syncthreads();

    // Phase 3: replay from incoming state; fuse sigmoid(r); emit fp16
    {
        float num0 = s_v[chunk][cp * 2], num1 = s_v[chunk][cp * 2 + 1];
        float den0 = s_d[chunk][cp * 2], den1 = s_d[chunk][cp * 2 + 1];
        float mx0  = s_m[chunk][cp * 2], mx1  = s_m[chunk][cp * 2 + 1];

#pragma unroll 2
        for (int t = 0; t < LCHK; t++) {
            size_t g = base + (size_t)t * CC;
            __half2 kh = *reinterpret_cast<const __half2*>(k + g);
            __half2 vh = *reinterpret_cast<const __half2*>(v + g);
            __half2 rh = *reinterpret_cast<const __half2*>(r + g);
            float k0 = __half2float(kh.x), k1 = __half2float(kh.y);
            float v0 = __half2float(vh.x), v1 = __half2float(vh.y);
            float r0 = __half2float(rh.x), r1 = __half2float(rh.y);

            float ku0 = k0 + u0, ku1 = k1 + u1;
            float mo0 = fmaxf(mx0, ku0), mo1 = fmaxf(mx1, ku1);
            float a10 = __expf(mx0 - mo0), a11 = __expf(mx1 - mo1);
            float a20 = __expf(ku0 - mo0), a21 = __expf(ku1 - mo1);
            float out0 = __fdividef(a10 * num0 + a20 * v0, a10 * den0 + a20);
            float out1 = __fdividef(a11 * num1 + a21 * v1, a11 * den1 + a21);

            float mw0 = mx0 + w0, mw1 = mx1 + w1;
            float ms0 = fmaxf(mw0, k0), ms1 = fmaxf(mw1, k1);
            float b10 = __expf(mw0 - ms0), b11 = __expf(mw1 - ms1);
            float b20 = __expf(k0 - ms0), b21 = __expf(k1 - ms1);
            num0 = b10 * num0 + b20 * v0;  num1 = b11 * num1 + b21 * v1;
            den0 = b10 * den0 + b20;       den1 = b11 * den1 + b21;
            mx0 = ms0;                     mx1 = ms1;

            float sr0 = __fdividef(1.f, 1.f + __expf(-r0));
            float sr1 = __fdividef(1.f, 1.f + __expf(-r1));
            __half2 sh = __floats2half2_rn(sr0 * out0, sr1 * out1);
            *reinterpret_cast<__half2*>(s + g) = sh;
        }
    }
}

// ---------------------------------------------------------------------------
// Launch
// ---------------------------------------------------------------------------
extern "C" void kernel_launch(void* const* d_in, const int* in_sizes, int n_in,
                              void* d_out, int out_size) {
    const float* x   = (const float*)d_in[0];
    const float* td  = (const float*)d_in[1];
    const float* tf  = (const float*)d_in[2];
    const float* tmk = (const float*)d_in[3];
    const float* tmv = (const float*)d_in[4];
    const float* tmr = (const float*)d_in[5];
    const float* Wk  = (const float*)d_in[6];
    const float* Wv  = (const float*)d_in[7];
    const float* Wr  = (const float*)d_in[8];
    const float* Wo  = (const float*)d_in[9];
    float* out = (float*)d_out;

    static bool inited = false;
    static __half *p_xk, *p_xv, *p_xr, *p_w, *p_s, *p_k16, *p_v16, *p_r16;
    if (!inited) {
        cudaGetSymbolAddress((void**)&p_xk, g_xk16);
        cudaGetSymbolAddress((void**)&p_xv, g_xv16);
        cudaGetSymbolAddress((void**)&p_xr, g_xr16);
        cudaGetSymbolAddress((void**)&p_w,  g_w16);
        cudaGetSymbolAddress((void**)&p_k16, g_k16);
        cudaGetSymbolAddress((void**)&p_v16, g_v16);
        cudaGetSymbolAddress((void**)&p_r16, g_r16);
        cudaGetSymbolAddress((void**)&p_s,  g_s16);
        cudaFuncSetAttribute(gemm_f16,
                             cudaFuncAttributeMaxDynamicSharedMemorySize, GSMEM);
        inited = true;
    }

    // 1. fused prep: mixing + weight conversion (16B stores throughout)
    prep_kernel<<<MIXBLK + CVTBLK, 256>>>(
        (const float4*)x, (const float4*)tmk, (const float4*)tmv, (const float4*)tmr,
        (const float4*)Wk, (const float4*)Wv, (const float4*)Wr, (const float4*)Wo,
        p_w);

    // 2. fused projection GEMMs (all fp16 outputs)
    {
        dim3 gg(CC / BN, MM / BM, 3);  // (16, 32, 3)
        gemm_f16<<<gg, GTHR, GSMEM>>>(p_xk, p_xv, p_xr, p_w,
                                      nullptr, p_k16, p_v16, p_r16, 1);
    }

    // 3. fused WKV scan (one kernel) + sigmoid fusion
    {
        int blocks = BB * (CC / WCHAN);  // 512
        wkv_fused<<<blocks, WTHR>>>(p_k16, p_v16, p_r16, td, tf, p_s);
    }

    // 4. output GEMM into d_out (fp32 epilogue)
    {
        dim3 gg(CC / BN, MM / BM, 1);
        gemm_f16<<<gg, GTHR, GSMEM>>>(p_s, p_s, p_s, p_w + 3ULL * CC * CC,
                                      out, nullptr, nullptr, nullptr, 0);
    }
}

// round 17
// speedup vs baseline: 1.1187x; 1.1187x over previous
#include <cuda_runtime.h>
#include <cuda_fp16.h>
#include <cstdint>

// Problem dims
#define BB 8
#define TT 1024
#define CC 2048
#define MM (BB * TT)          // 8192
#define NELEM (BB * TT * CC)  // 16,777,216

// WKV chunking
#define NCHK 32
#define LCHK (TT / NCHK)      // 32
#define WCHAN 32              // channels per wkv block
#define WTHR (NCHK * WCHAN / 2)  // 512 threads

// GEMM tiling (HMMA mma.sync, fp16, BK=64, 3-stage pipeline)
#define BM 128
#define BN 128
#define BKK 64
#define NITER (CC / BKK)      // 32
#define SROWB 144             // 64 fp16 = 128B + 16B pad
#define TILEB (128 * SROWB)   // 18432
#define STAGEB (2 * TILEB)    // 36864 (A + B)
#define NSTAGE 3
#define GSMEM (NSTAGE * STAGEB)  // 110592

#define MIXBLK ((NELEM / 8) / 256)       // 8192 blocks for mixing (8 elem/thr)
#define CVTBLK ((4 * CC * CC / 8) / 256) // 8192 blocks for weight cvt

// ---------------------------------------------------------------------------
// Scratch (static device globals; no allocation anywhere)
// ---------------------------------------------------------------------------
__device__ __half g_xk16[NELEM], g_xv16[NELEM], g_xr16[NELEM];
__device__ __half g_w16[4ULL * CC * CC];
__device__ __half g_k16[NELEM], g_v16[NELEM], g_r16[NELEM];
__device__ __half g_s16[NELEM];

// ---------------------------------------------------------------------------
// Helpers
// ---------------------------------------------------------------------------
__device__ __forceinline__ uint32_t smem_u32(const void* p) {
    uint32_t a;
    asm("{ .reg .u64 t; cvta.to.shared.u64 t, %1; cvt.u32.u64 %0, t; }"
        : "=r"(a) : "l"(p));
    return a;
}
__device__ __forceinline__ void cp_async16(uint32_t saddr, const void* gaddr) {
    asm volatile("cp.async.cg.shared.global [%0], [%1], 16;"
                 :: "r"(saddr), "l"(gaddr));
}
__device__ __forceinline__ void cp_commit() { asm volatile("cp.async.commit_group;"); }
__device__ __forceinline__ void cp_wait1() { asm volatile("cp.async.wait_group 1;"); }
__device__ __forceinline__ void cp_wait0() { asm volatile("cp.async.wait_group 0;"); }

__device__ __forceinline__ void ldsm_x4(uint32_t addr, uint32_t& r0, uint32_t& r1,
                                        uint32_t& r2, uint32_t& r3) {
    asm volatile("ldmatrix.sync.aligned.m8n8.x4.shared.b16 {%0,%1,%2,%3}, [%4];"
                 : "=r"(r0), "=r"(r1), "=r"(r2), "=r"(r3) : "r"(addr));
}
__device__ __forceinline__ void mma_f16(float* c, const uint32_t* a, const uint32_t* b) {
    asm volatile(
        "mma.sync.aligned.m16n8k16.row.col.f32.f16.f16.f32 "
        "{%0,%1,%2,%3}, {%4,%5,%6,%7}, {%8,%9}, {%0,%1,%2,%3};"
        : "+f"(c[0]), "+f"(c[1]), "+f"(c[2]), "+f"(c[3])
        : "r"(a[0]), "r"(a[1]), "r"(a[2]), "r"(a[3]), "r"(b[0]), "r"(b[1]));
}

// pack 8 floats -> one 16B store of 8 fp16
__device__ __forceinline__ void store_h8(__half* __restrict__ dst, size_t base,
                                         float4 a, float4 b) {
    __half2 h0 = __floats2half2_rn(a.x, a.y);
    __half2 h1 = __floats2half2_rn(a.z, a.w);
    __half2 h2 = __floats2half2_rn(b.x, b.y);
    __half2 h3 = __floats2half2_rn(b.z, b.w);
    uint4 u;
    u.x = *reinterpret_cast<uint32_t*>(&h0);
    u.y = *reinterpret_cast<uint32_t*>(&h1);
    u.z = *reinterpret_cast<uint32_t*>(&h2);
    u.w = *reinterpret_cast<uint32_t*>(&h3);
    *reinterpret_cast<uint4*>(dst + base) = u;
}

__device__ __forceinline__ float4 mix4(float4 xc, float4 xs, float4 m) {
    float4 o;
    o.x = xc.x * m.x + xs.x * (1.f - m.x);
    o.y = xc.y * m.y + xs.y * (1.f - m.y);
    o.z = xc.z * m.z + xs.z * (1.f - m.z);
    o.w = xc.w * m.w + xs.w * (1.f - m.w);
    return o;
}

// ---------------------------------------------------------------------------
// Kernel: fused prep — blocks [0, MIXBLK) do time-shift mixing (+cvt),
// blocks [MIXBLK, MIXBLK+CVTBLK) convert the 4 weight matrices.
// 8 elements per thread; all stores are 16B.
// ---------------------------------------------------------------------------
__global__ void prep_kernel(const float4* __restrict__ x4,
                            const float4* __restrict__ tmk4,
                            const float4* __restrict__ tmv4,
                            const float4* __restrict__ tmr4,
                            const float4* __restrict__ w0,
                            const float4* __restrict__ w1,
                            const float4* __restrict__ w2,
                            const float4* __restrict__ w3,
                            __half* __restrict__ wdst) {
    const int blk = blockIdx.x;
    if (blk < MIXBLK) {
        const int C4 = CC / 4;      // 512 float4 per row
        const int C8 = CC / 8;      // 256 groups of 8 per row
        int i = blk * 256 + threadIdx.x;        // [0, NELEM/8)
        int c8 = i % C8;
        int t = (i / C8) % TT;
        int b4 = i * 2;                          // float4 index of first half

        float4 xc0 = x4[b4], xc1 = x4[b4 + 1];
        float4 xs0 = make_float4(0.f, 0.f, 0.f, 0.f);
        float4 xs1 = xs0;
        if (t > 0) { xs0 = x4[b4 - C4]; xs1 = x4[b4 + 1 - C4]; }

        float4 mk0 = tmk4[c8 * 2], mk1 = tmk4[c8 * 2 + 1];
        float4 mv0 = tmv4[c8 * 2], mv1 = tmv4[c8 * 2 + 1];
        float4 mr0 = tmr4[c8 * 2], mr1 = tmr4[c8 * 2 + 1];

        size_t base = (size_t)i * 8;
        store_h8(g_xk16, base, mix4(xc0, xs0, mk0), mix4(xc1, xs1, mk1));
        store_h8(g_xv16, base, mix4(xc0, xs0, mv0), mix4(xc1, xs1, mv1));
        store_h8(g_xr16, base, mix4(xc0, xs0, mr0), mix4(xc1, xs1, mr1));
    } else {
        const int n8 = CC * CC / 8;
        int i = (blk - MIXBLK) * 256 + threadIdx.x;   // [0, 4*n8)
        int m = i / n8;
        int o = i - m * n8;
        const float4* src = (m == 0) ? w0 : (m == 1) ? w1 : (m == 2) ? w2 : w3;
        store_h8(wdst, (size_t)i * 8, src[o * 2], src[o * 2 + 1]);
    }
}

// ---------------------------------------------------------------------------
// Kernel: fp16 HMMA GEMM, BK=64, 3-stage cp.async pipeline, one sync/iter.
// Ordering wait -> sync -> issue -> consume is the provably-minimal
// single-barrier schedule: cp.async waits are PER-THREAD, so the barrier
// after the wait is what publishes all threads' arrivals; the same barrier
// proves stage j-1 is consumed so nbuf may be refilled. (R16's reorder
// violated this and produced NaN.)
// proj=1: gridDim.z selects (A,B,Ch); all outputs fp16.
// proj=0: fp32 output (the final Wo GEMM into d_out).
// ---------------------------------------------------------------------------
__global__ __launch_bounds__(256, 2)
void gemm_f16(const __half* __restrict__ A0, const __half* __restrict__ A1,
              const __half* __restrict__ A2, const __half* __restrict__ Bbase,
              float* __restrict__ Cf, __half* __restrict__ Ch0,
              __half* __restrict__ Ch1, __half* __restrict__ Ch2, int proj) {
    extern __shared__ __align__(128) char smem[];
    const uint32_t sb = smem_u32(smem);
    const int z = blockIdx.z;
    const __half* A = (z == 0) ? A0 : (z == 1) ? A1 : A2;
    const __half* B = Bbase + (size_t)z * CC * CC;

    const int tid = threadIdx.x;
    const int wid = tid >> 5;
    const int lane = tid & 31;
    const int wm = wid >> 2;
    const int wn = wid & 3;
    const int rowBase = blockIdx.y * BM;
    const int colBase = blockIdx.x * BN;
    const int warpRow = wm * 64;
    const int warpCol = wn * 32;

    const uint32_t OF_A = 0, OF_B = TILEB;

    auto issue_stage = [&](int buf, int k0) {
        uint32_t sbase = sb + buf * STAGEB;
#pragma unroll
        for (int it = 0; it < 4; it++) {
            int idx = tid + it * 256;
            int r = idx >> 3, c = idx & 7;
            uint32_t so = (uint32_t)(r * SROWB + c * 16);
            size_t gA = (size_t)(rowBase + r) * CC + k0 + c * 8;
            size_t gB = (size_t)(colBase + r) * CC + k0 + c * 8;
            cp_async16(sbase + OF_A + so, A + gA);
            cp_async16(sbase + OF_B + so, B + gB);
        }
        cp_commit();
    };

    float acc[4][4][4];
#pragma unroll
    for (int i = 0; i < 4; i++)
#pragma unroll
        for (int j = 0; j < 4; j++)
#pragma unroll
            for (int q = 0; q < 4; q++) acc[i][j][q] = 0.f;

    const uint32_t aLaneOff =
        (uint32_t)((warpRow + (lane & 15)) * SROWB + (lane >> 4) * 16);
    const int bg = lane >> 3, bw = lane & 7;
    const uint32_t bLaneOff =
        (uint32_t)((warpCol + (bg >> 1) * 8 + bw) * SROWB + (bg & 1) * 16);

    issue_stage(0, 0);
    issue_stage(1, BKK);

    int buf = 0, nbuf = 2;
#pragma unroll 1
    for (int j = 0; j < NITER; j++) {
        if (j + 2 < NITER) cp_wait1(); else cp_wait0();
        __syncthreads();
        if (j + 2 < NITER) issue_stage(nbuf, (j + 2) * BKK);

        const uint32_t sbase = sb + buf * STAGEB;
#pragma unroll
        for (int kk = 0; kk < 4; kk++) {
            const uint32_t kOff = kk * 32;
            uint32_t ah[4][4], bx[4][2];
#pragma unroll
            for (int i = 0; i < 4; i++) {
                uint32_t ad = sbase + OF_A + aLaneOff + i * 16 * SROWB + kOff;
                ldsm_x4(ad, ah[i][0], ah[i][1], ah[i][2], ah[i][3]);
            }
#pragma unroll
            for (int jp = 0; jp < 2; jp++) {
                uint32_t bd = sbase + OF_B + bLaneOff + jp * 16 * SROWB + kOff;
                ldsm_x4(bd, bx[jp * 2][0], bx[jp * 2][1],
                        bx[jp * 2 + 1][0], bx[jp * 2 + 1][1]);
            }
#pragma unroll
            for (int i = 0; i < 4; i++)
#pragma unroll
                for (int jj = 0; jj < 4; jj++) mma_f16(acc[i][jj], ah[i], bx[jj]);
        }
        buf = (buf == NSTAGE - 1) ? 0 : buf + 1;
        nbuf = (nbuf == NSTAGE - 1) ? 0 : nbuf + 1;
    }

    const int er = lane >> 2, ec = (lane & 3) * 2;
    if (proj) {
        __half* Ch = (z == 0) ? Ch0 : (z == 1) ? Ch1 : Ch2;
#pragma unroll
        for (int i = 0; i < 4; i++) {
#pragma unroll
            for (int jj = 0; jj < 4; jj++) {
                size_t row0 = (size_t)(rowBase + warpRow + i * 16 + er);
                size_t col = (size_t)(colBase + warpCol + jj * 8 + ec);
                __half2 v0 = __floats2half2_rn(acc[i][jj][0], acc[i][jj][1]);
                __half2 v1 = __floats2half2_rn(acc[i][jj][2], acc[i][jj][3]);
                *reinterpret_cast<__half2*>(Ch + row0 * CC + col) = v0;
                *reinterpret_cast<__half2*>(Ch + (row0 + 8) * CC + col) = v1;
            }
        }
    } else {
#pragma unroll
        for (int i = 0; i < 4; i++) {
#pragma unroll
            for (int jj = 0; jj < 4; jj++) {
                size_t row0 = (size_t)(rowBase + warpRow + i * 16 + er);
                size_t col = (size_t)(colBase + warpCol + jj * 8 + ec);
                float2 v0 = make_float2(acc[i][jj][0], acc[i][jj][1]);
                float2 v1 = make_float2(acc[i][jj][2], acc[i][jj][3]);
                *reinterpret_cast<float2*>(Cf + row0 * CC + col) = v0;
                *reinterpret_cast<float2*>(Cf + (row0 + 8) * CC + col) = v1;
            }
        }
    }
}

// ---------------------------------------------------------------------------
// Kernel: fused WKV — all 3 phases in one block per (batch, 32 channels).
// ---------------------------------------------------------------------------
__global__ __launch_bounds__(WTHR)
void wkv_fused(const __half* __restrict__ k,
               const __half* __restrict__ v,
               const __half* __restrict__ r,
               const float* __restrict__ time_decay,
               const float* __restrict__ time_first,
               __half* __restrict__ s) {
    __shared__ float s_v[NCHK][WCHAN];
    __shared__ float s_d[NCHK][WCHAN];
    __shared__ float s_m[NCHK][WCHAN];

    const int b = blockIdx.x / (CC / WCHAN);
    const int cbase = (blockIdx.x % (CC / WCHAN)) * WCHAN;
    const int tid = threadIdx.x;
    const int chunk = tid >> 4;       // 0..31
    const int cp = tid & 15;          // 0..15
    const int c = cbase + cp * 2;

    const float w0 = -__expf(time_decay[c]);
    const float w1 = -__expf(time_decay[c + 1]);
    const float u0 = time_first[c];
    const float u1 = time_first[c + 1];

    const size_t base = ((size_t)b * TT + chunk * LCHK) * CC + c;

    // Phase 1: local sums (zero initial state)
    {
        float sv0 = 0.f, sd0 = 0.f, m0 = -1e38f;
        float sv1 = 0.f, sd1 = 0.f, m1 = -1e38f;
#pragma unroll 4
        for (int t = 0; t < LCHK; t++) {
            size_t g = base + (size_t)t * CC;
            __half2 kh = *reinterpret_cast<const __half2*>(k + g);
            __half2 vh = *reinterpret_cast<const __half2*>(v + g);
            float k0 = __half2float(kh.x), k1 = __half2float(kh.y);
            float v0 = __half2float(vh.x), v1 = __half2float(vh.y);

            float mw0 = m0 + w0, mw1 = m1 + w1;
            float mn0 = fmaxf(mw0, k0), mn1 = fmaxf(mw1, k1);
            float e10 = __expf(mw0 - mn0), e11 = __expf(mw1 - mn1);
            float e20 = __expf(k0 - mn0), e21 = __expf(k1 - mn1);
            sv0 = e10 * sv0 + e20 * v0;  sv1 = e11 * sv1 + e21 * v1;
            sd0 = e10 * sd0 + e20;       sd1 = e11 * sd1 + e21;
            m0 = mn0;                    m1 = mn1;
        }
        s_v[chunk][cp * 2] = sv0;  s_v[chunk][cp * 2 + 1] = sv1;
        s_d[chunk][cp * 2] = sd0;  s_d[chunk][cp * 2 + 1] = sd1;
        s_m[chunk][cp * 2] = m0;   s_m[chunk][cp * 2 + 1] = m1;
    }
    __syncthreads();

    // Phase 2: in-place prefix over chunks; 32 threads, one channel each.
    if (tid < WCHAN) {
        const float w = -__expf(time_decay[cbase + tid]);
        const float Lw = (float)LCHK * w;
        float num = 0.f, den = 0.f, mx = -1e38f;
#pragma unroll
        for (int ch = 0; ch < NCHK; ch++) {
            float svv = s_v[ch][tid];
            float sdd = s_d[ch][tid];
            float smm = s_m[ch][tid];
            s_v[ch][tid] = num;
            s_d[ch][tid] = den;
            s_m[ch][tid] = mx;
            float mo = mx + Lw;
            float mn = fmaxf(mo, smm);
            float e1 = __expf(mo - mn);
            float e2 = __expf(smm - mn);
            num = e1 * num + e2 * svv;
            den = e1 * den + e2 * sdd;
            mx = mn;
        }
    }
    __syncthreads();

    // Phase 3: replay from incoming state; fuse sigmoid(r); emit fp16
    {
        float num0 = s_v[chunk][cp * 2], num1 = s_v[chunk][cp * 2 + 1];
        float den0 = s_d[chunk][cp * 2], den1 = s_d[chunk][cp * 2 + 1];
        float mx0  = s_m[chunk][cp * 2], mx1  = s_m[chunk][cp * 2 + 1];

#pragma unroll 2
        for (int t = 0; t < LCHK; t++) {
            size_t g = base + (size_t)t * CC;
            __half2 kh = *reinterpret_cast<const __half2*>(k + g);
            __half2 vh = *reinterpret_cast<const __half2*>(v + g);
            __half2 rh = *reinterpret_cast<const __half2*>(r + g);
            float k0 = __half2float(kh.x), k1 = __half2float(kh.y);
            float v0 = __half2float(vh.x), v1 = __half2float(vh.y);
            float r0 = __half2float(rh.x), r1 = __half2float(rh.y);

            float ku0 = k0 + u0, ku1 = k1 + u1;
            float mo0 = fmaxf(mx0, ku0), mo1 = fmaxf(mx1, ku1);
            float a10 = __expf(mx0 - mo0), a11 = __expf(mx1 - mo1);
            float a20 = __expf(ku0 - mo0), a21 = __expf(ku1 - mo1);
            float out0 = __fdividef(a10 * num0 + a20 * v0, a10 * den0 + a20);
            float out1 = __fdividef(a11 * num1 + a21 * v1, a11 * den1 + a21);

            float mw0 = mx0 + w0, mw1 = mx1 + w1;
            float ms0 = fmaxf(mw0, k0), ms1 = fmaxf(mw1, k1);
            float b10 = __expf(mw0 - ms0), b11 = __expf(mw1 - ms1);
            float b20 = __expf(k0 - ms0), b21 = __expf(k1 - ms1);
            num0 = b10 * num0 + b20 * v0;  num1 = b11 * num1 + b21 * v1;
            den0 = b10 * den0 + b20;       den1 = b11 * den1 + b21;
            mx0 = ms0;                     mx1 = ms1;

            float sr0 = __fdividef(1.f, 1.f + __expf(-r0));
            float sr1 = __fdividef(1.f, 1.f + __expf(-r1));
            __half2 sh = __floats2half2_rn(sr0 * out0, sr1 * out1);
            *reinterpret_cast<__half2*>(s + g) = sh;
        }
    }
}

// ---------------------------------------------------------------------------
// Launch
// ---------------------------------------------------------------------------
extern "C" void kernel_launch(void* const* d_in, const int* in_sizes, int n_in,
                              void* d_out, int out_size) {
    const float* x   = (const float*)d_in[0];
    const float* td  = (const float*)d_in[1];
    const float* tf  = (const float*)d_in[2];
    const float* tmk = (const float*)d_in[3];
    const float* tmv = (const float*)d_in[4];
    const float* tmr = (const float*)d_in[5];
    const float* Wk  = (const float*)d_in[6];
    const float* Wv  = (const float*)d_in[7];
    const float* Wr  = (const float*)d_in[8];
    const float* Wo  = (const float*)d_in[9];
    float* out = (float*)d_out;

    static bool inited = false;
    static __half *p_xk, *p_xv, *p_xr, *p_w, *p_s, *p_k16, *p_v16, *p_r16;
    if (!inited) {
        cudaGetSymbolAddress((void**)&p_xk, g_xk16);
        cudaGetSymbolAddress((void**)&p_xv, g_xv16);
        cudaGetSymbolAddress((void**)&p_xr, g_xr16);
        cudaGetSymbolAddress((void**)&p_w,  g_w16);
        cudaGetSymbolAddress((void**)&p_k16, g_k16);
        cudaGetSymbolAddress((void**)&p_v16, g_v16);
        cudaGetSymbolAddress((void**)&p_r16, g_r16);
        cudaGetSymbolAddress((void**)&p_s,  g_s16);
        cudaFuncSetAttribute(gemm_f16,
                             cudaFuncAttributeMaxDynamicSharedMemorySize, GSMEM);
        inited = true;
    }

    // 1. fused prep: mixing + weight conversion (16B stores throughout)
    prep_kernel<<<MIXBLK + CVTBLK, 256>>>(
        (const float4*)x, (const float4*)tmk, (const float4*)tmv, (const float4*)tmr,
        (const float4*)Wk, (const float4*)Wv, (const float4*)Wr, (const float4*)Wo,
        p_w);

    // 2. fused projection GEMMs (all fp16 outputs)
    {
        dim3 gg(CC / BN, MM / BM, 3);  // (16, 64, 3)
        gemm_f16<<<gg, 256, GSMEM>>>(p_xk, p_xv, p_xr, p_w,
                                     nullptr, p_k16, p_v16, p_r16, 1);
    }

    // 3. fused WKV scan (one kernel) + sigmoid fusion
    {
        int blocks = BB * (CC / WCHAN);  // 512
        wkv_fused<<<blocks, WTHR>>>(p_k16, p_v16, p_r16, td, tf, p_s);
    }

    // 4. output GEMM into d_out (fp32 epilogue)
    {
        dim3 gg(CC / BN, MM / BM, 1);
        gemm_f16<<<gg, 256, GSMEM>>>(p_s, p_s, p_s, p_w + 3ULL * CC * CC,
                                     out, nullptr, nullptr, nullptr, 0);
    }
}